// round 8
// baseline (speedup 1.0000x reference)
#include <cuda_runtime.h>
#include <cuda_fp16.h>
#include <math.h>

#define NNODES 50000
#define NEDGES 800000

// ---------------- device scratch (no allocations allowed) ----------------
__device__ int     g_deg[NNODES];
__device__ int     g_rowptr[NNODES + 1];
__device__ int     g_wr[NNODES];
__device__ int     g_srcs[NEDGES];
__device__ __half2 g_hfh[NNODES * 64];  // transformed features, fp16 [N][128]
__device__ float   g_h1[NNODES * 128];  // layer-1 output (relu) = layer-2 input (fp32)
__device__ float   g_el[NNODES * 4];
__device__ float   g_er[NNODES * 4];

// ---------------- CSR build ----------------
__global__ void k_zero_deg() {
    int i = blockIdx.x * blockDim.x + threadIdx.x;
    if (i < NNODES) g_deg[i] = 0;
}

__global__ void k_hist(const int* __restrict__ dst) {
    int i = blockIdx.x * blockDim.x + threadIdx.x;
    if (i < NEDGES) atomicAdd(&g_deg[dst[i]], 1);
}

// single-block exclusive scan of g_deg -> g_rowptr (and g_wr copy)
__global__ void k_scan() {
    __shared__ int ssum[1024];
    int tid = threadIdx.x;
    const int CH = (NNODES + 1023) / 1024;   // 49
    int base = tid * CH;
    int local = 0;
    for (int i = 0; i < CH; i++) {
        int idx = base + i;
        if (idx < NNODES) local += g_deg[idx];
    }
    ssum[tid] = local;
    __syncthreads();
    for (int off = 1; off < 1024; off <<= 1) {
        int v = (tid >= off) ? ssum[tid - off] : 0;
        __syncthreads();
        ssum[tid] += v;
        __syncthreads();
    }
    int run = ssum[tid] - local;   // exclusive prefix
    for (int i = 0; i < CH; i++) {
        int idx = base + i;
        if (idx < NNODES) {
            g_rowptr[idx] = run;
            g_wr[idx] = run;
            run += g_deg[idx];
        }
    }
    if (tid == 1023) g_rowptr[NNODES] = ssum[1023];
}

__global__ void k_fill(const int* __restrict__ src, const int* __restrict__ dst) {
    int i = blockIdx.x * blockDim.x + threadIdx.x;
    if (i < NEDGES) {
        int d = dst[i];
        int p = atomicAdd(&g_wr[d], 1);
        g_srcs[p] = src[i];
    }
}

// ---------------- tensor-core GEMM: hf = feat @ W (+ el/er epilogue) --------
// mma.sync.m16n8k16 fp16 inputs, fp32 accumulate. Block: 256 thr (8 warps),
// 64 rows x 128 cols per block. Warp (wm 0..3, wn 0..1) owns a 16x64 C tile.
// A: row-major k-contiguous, stride 136 halves. B: TRANSPOSED n-major
// (sBt[n][k], stride 138 halves) so each mma B fragment is ONE 32-bit LDS.
#define SA_STRIDE 136
#define SB_STRIDE 138
#define GEMM_SMEM (64 * SA_STRIDE * 2 + 128 * SB_STRIDE * 2)   // 52736 bytes

__device__ __forceinline__ void mma16816(float* c, unsigned a0, unsigned a1,
                                         unsigned a2, unsigned a3,
                                         unsigned b0, unsigned b1) {
    asm volatile(
        "mma.sync.aligned.m16n8k16.row.col.f32.f16.f16.f32 "
        "{%0,%1,%2,%3}, {%4,%5,%6,%7}, {%8,%9}, {%0,%1,%2,%3};"
        : "+f"(c[0]), "+f"(c[1]), "+f"(c[2]), "+f"(c[3])
        : "r"(a0), "r"(a1), "r"(a2), "r"(a3), "r"(b0), "r"(b1));
}

__global__ void __launch_bounds__(256) k_gemm(const float* __restrict__ feat,
                                              const float* __restrict__ W,
                                              const float* __restrict__ al,
                                              const float* __restrict__ ar) {
    extern __shared__ __half sh[];
    __half* sA  = sh;                      // 64 x 136 (row-major, k contiguous)
    __half* sBt = sh + 64 * SA_STRIDE;     // 128 x 138 (n-major, k contiguous)
    int tid = threadIdx.x;
    int row0 = blockIdx.x * 64;

    // fill sBt transposed: thread handles a k-pair x 4-n group.
    // reads 2 coalesced float4 rows of W, writes 4 half2 (k-pair) stores.
    const float4* W4 = (const float4*)W;
    #pragma unroll 4
    for (int i = tid; i < 2048; i += 256) {
        int kp = i >> 5, c4 = i & 31;
        int k = kp * 2;
        float4 w0 = W4[k * 32 + c4];
        float4 w1 = W4[(k + 1) * 32 + c4];
        int n = c4 * 4;
        *(__half2*)&sBt[(n + 0) * SB_STRIDE + k] = __floats2half2_rn(w0.x, w1.x);
        *(__half2*)&sBt[(n + 1) * SB_STRIDE + k] = __floats2half2_rn(w0.y, w1.y);
        *(__half2*)&sBt[(n + 2) * SB_STRIDE + k] = __floats2half2_rn(w0.z, w1.z);
        *(__half2*)&sBt[(n + 3) * SB_STRIDE + k] = __floats2half2_rn(w0.w, w1.w);
    }
    // fill sA = feat tile [64 x 128] fp16
    const float4* F4 = (const float4*)feat;
    #pragma unroll 2
    for (int i = tid; i < 2048; i += 256) {
        int r = i >> 5, c4 = i & 31;
        int gr = row0 + r;
        float4 f = (gr < NNODES) ? F4[gr * 32 + c4] : make_float4(0.f, 0.f, 0.f, 0.f);
        *(__half2*)&sA[r * SA_STRIDE + c4 * 4]     = __floats2half2_rn(f.x, f.y);
        *(__half2*)&sA[r * SA_STRIDE + c4 * 4 + 2] = __floats2half2_rn(f.z, f.w);
    }
    __syncthreads();

    int warp = tid >> 5, lane = tid & 31;
    int wm = warp >> 1, wn = warp & 1;
    int g = lane >> 2, t2 = (lane & 3) * 2;
    int mbase = wm * 16;
    int nbase = wn * 64;

    float acc[8][4];
    #pragma unroll
    for (int j = 0; j < 8; j++) {
        acc[j][0] = acc[j][1] = acc[j][2] = acc[j][3] = 0.f;
    }

    #pragma unroll
    for (int ks = 0; ks < 8; ks++) {
        int k0 = ks * 16;
        unsigned a0 = *(unsigned*)&sA[(mbase + g) * SA_STRIDE + k0 + t2];
        unsigned a1 = *(unsigned*)&sA[(mbase + g + 8) * SA_STRIDE + k0 + t2];
        unsigned a2 = *(unsigned*)&sA[(mbase + g) * SA_STRIDE + k0 + t2 + 8];
        unsigned a3 = *(unsigned*)&sA[(mbase + g + 8) * SA_STRIDE + k0 + t2 + 8];
        #pragma unroll
        for (int j = 0; j < 8; j++) {
            int n = nbase + j * 8 + g;
            unsigned b0 = *(unsigned*)&sBt[n * SB_STRIDE + k0 + t2];
            unsigned b1 = *(unsigned*)&sBt[n * SB_STRIDE + k0 + t2 + 8];
            mma16816(acc[j], a0, a1, a2, a3, b0, b1);
        }
    }

    // epilogue: rows r0 = row0+mbase+g, r1 = r0+8. Store fp16 hf; el/er from fp32.
    int r0 = row0 + mbase + g;
    int r1 = r0 + 8;
    __half* hf = (__half*)g_hfh;
    float el0a = 0.f, er0a = 0.f, el1a = 0.f, er1a = 0.f;  // head h0
    float el0b = 0.f, er0b = 0.f, el1b = 0.f, er1b = 0.f;  // head h0+1
    #pragma unroll
    for (int j = 0; j < 8; j++) {
        int n = nbase + j * 8 + t2;
        if (r0 < NNODES)
            *(__half2*)&hf[r0 * 128 + n] = __floats2half2_rn(acc[j][0], acc[j][1]);
        if (r1 < NNODES)
            *(__half2*)&hf[r1 * 128 + n] = __floats2half2_rn(acc[j][2], acc[j][3]);
        float av0 = __ldg(&al[n]), av1 = __ldg(&al[n + 1]);
        float rv0 = __ldg(&ar[n]), rv1 = __ldg(&ar[n + 1]);
        float pe0 = acc[j][0] * av0 + acc[j][1] * av1;
        float pr0 = acc[j][0] * rv0 + acc[j][1] * rv1;
        float pe1 = acc[j][2] * av0 + acc[j][3] * av1;
        float pr1 = acc[j][2] * rv0 + acc[j][3] * rv1;
        if (j < 4) { el0a += pe0; er0a += pr0; el1a += pe1; er1a += pr1; }
        else       { el0b += pe0; er0b += pr0; el1b += pe1; er1b += pr1; }
    }
    #pragma unroll
    for (int off = 1; off <= 2; off <<= 1) {
        el0a += __shfl_xor_sync(0xffffffffu, el0a, off);
        er0a += __shfl_xor_sync(0xffffffffu, er0a, off);
        el1a += __shfl_xor_sync(0xffffffffu, el1a, off);
        er1a += __shfl_xor_sync(0xffffffffu, er1a, off);
        el0b += __shfl_xor_sync(0xffffffffu, el0b, off);
        er0b += __shfl_xor_sync(0xffffffffu, er0b, off);
        el1b += __shfl_xor_sync(0xffffffffu, el1b, off);
        er1b += __shfl_xor_sync(0xffffffffu, er1b, off);
    }
    if ((lane & 3) == 0) {
        int h0 = wn * 2;
        if (r0 < NNODES) {
            g_el[r0 * 4 + h0]     = el0a;  g_er[r0 * 4 + h0]     = er0a;
            g_el[r0 * 4 + h0 + 1] = el0b;  g_er[r0 * 4 + h0 + 1] = er0b;
        }
        if (r1 < NNODES) {
            g_el[r1 * 4 + h0]     = el1a;  g_er[r1 * 4 + h0]     = er1a;
            g_el[r1 * 4 + h0 + 1] = el1b;  g_er[r1 * 4 + h0 + 1] = er1b;
        }
    }
}

// ---------------- warp-per-dst aggregation (R5 version — best) ----------------
__device__ __forceinline__ float lrelu(float x) { return x > 0.f ? x : 0.2f * x; }

template <bool FINAL>
__global__ void __launch_bounds__(256) k_agg(const float* __restrict__ bias,
                                             const float* __restrict__ Wout,
                                             const float* __restrict__ bout,
                                             float* __restrict__ outp) {
    int gw = (blockIdx.x * blockDim.x + threadIdx.x) >> 5;
    int lane = threadIdx.x & 31;
    if (gw >= NNODES) return;
    int n = gw;
    int start = g_rowptr[n], end = g_rowptr[n + 1];
    int h = lane >> 3;
    float er_h = __ldg(&g_er[n * 4 + h]);

    float den = 0.f;
    float4 acc = make_float4(0.f, 0.f, 0.f, 0.f);
    #pragma unroll 4
    for (int j = start; j < end; j++) {
        int s = __ldg(&g_srcs[j]);
        float el = __ldg(&g_el[s * 4 + h]);
        float x = __expf(lrelu(el + er_h));
        den += x;
        uint2 pk = __ldg((const uint2*)(g_hfh + s * 64) + lane);
        float2 v0 = __half22float2(*(__half2*)&pk.x);
        float2 v1 = __half22float2(*(__half2*)&pk.y);
        acc.x += v0.x * x; acc.y += v0.y * x;
        acc.z += v1.x * x; acc.w += v1.y * x;
    }

    float inv = 1.0f / fmaxf(den, 1e-30f);
    float4 b4 = ((const float4*)bias)[lane];
    float4 val;
    val.x = acc.x * inv + b4.x;
    val.y = acc.y * inv + b4.y;
    val.z = acc.z * inv + b4.z;
    val.w = acc.w * inv + b4.w;

    if (!FINAL) {
        val.x = fmaxf(val.x, 0.f); val.y = fmaxf(val.y, 0.f);
        val.z = fmaxf(val.z, 0.f); val.w = fmaxf(val.w, 0.f);
        ((float4*)g_h1)[n * 32 + lane] = val;
    } else {
        // mean over heads (lanes differing in bits 3,4 hold other heads, same d)
        #pragma unroll
        for (int off = 8; off <= 16; off <<= 1) {
            val.x += __shfl_xor_sync(0xffffffffu, val.x, off);
            val.y += __shfl_xor_sync(0xffffffffu, val.y, off);
            val.z += __shfl_xor_sync(0xffffffffu, val.z, off);
            val.w += __shfl_xor_sync(0xffffffffu, val.w, off);
        }
        val.x = fmaxf(val.x * 0.25f, 0.f);
        val.y = fmaxf(val.y * 0.25f, 0.f);
        val.z = fmaxf(val.z * 0.25f, 0.f);
        val.w = fmaxf(val.w * 0.25f, 0.f);
        int d0 = (lane & 7) * 4;
        float l0 = val.x * Wout[(d0 + 0) * 2 + 0] + val.y * Wout[(d0 + 1) * 2 + 0]
                 + val.z * Wout[(d0 + 2) * 2 + 0] + val.w * Wout[(d0 + 3) * 2 + 0];
        float l1 = val.x * Wout[(d0 + 0) * 2 + 1] + val.y * Wout[(d0 + 1) * 2 + 1]
                 + val.z * Wout[(d0 + 2) * 2 + 1] + val.w * Wout[(d0 + 3) * 2 + 1];
        #pragma unroll
        for (int off = 4; off >= 1; off >>= 1) {
            l0 += __shfl_xor_sync(0xffffffffu, l0, off, 8);
            l1 += __shfl_xor_sync(0xffffffffu, l1, off, 8);
        }
        if (lane == 0) {
            l0 += bout[0];
            l1 += bout[1];
            float m = fmaxf(l0, l1);
            float e0 = __expf(l0 - m), e1 = __expf(l1 - m);
            float s = e0 + e1;
            outp[n * 2 + 0] = e0 / s;
            outp[n * 2 + 1] = e1 / s;
        }
    }
}

// ---------------- launch ----------------
extern "C" void kernel_launch(void* const* d_in, const int* in_sizes, int n_in,
                              void* d_out, int out_size) {
    const float* in_feat = (const float*)d_in[0];
    const float* W1   = (const float*)d_in[1];
    const float* al1  = (const float*)d_in[2];
    const float* ar1  = (const float*)d_in[3];
    const float* b1   = (const float*)d_in[4];
    const float* W2   = (const float*)d_in[5];
    const float* al2  = (const float*)d_in[6];
    const float* ar2  = (const float*)d_in[7];
    const float* b2   = (const float*)d_in[8];
    const float* Wout = (const float*)d_in[9];
    const float* bout = (const float*)d_in[10];
    const int*   src  = (const int*)d_in[11];
    const int*   dst  = (const int*)d_in[12];
    float* out = (float*)d_out;

    cudaFuncSetAttribute(k_gemm, cudaFuncAttributeMaxDynamicSharedMemorySize, GEMM_SMEM);

    float* h1_ptr = nullptr;
    cudaGetSymbolAddress((void**)&h1_ptr, g_h1);

    int gemm_blocks = (NNODES + 63) / 64;
    int agg_blocks = (NNODES * 32 + 255) / 256;

    // CSR + layer 1 (gemm1 before k_fill: no CSR dependency; keeps k_gemm in
    // the ncu capture slot for direct verification of this round's change)
    k_zero_deg<<<(NNODES + 255) / 256, 256>>>();
    k_hist<<<(NEDGES + 255) / 256, 256>>>(dst);
    k_scan<<<1, 1024>>>();
    k_gemm<<<gemm_blocks, 256, GEMM_SMEM>>>(in_feat, W1, al1, ar1);
    k_fill<<<(NEDGES + 255) / 256, 256>>>(src, dst);
    k_agg<false><<<agg_blocks, 256>>>(b1, Wout, bout, out);

    // layer 2 + head-mean + projection + softmax
    k_gemm<<<gemm_blocks, 256, GEMM_SMEM>>>(h1_ptr, W2, al2, ar2);
    k_agg<true><<<agg_blocks, 256>>>(b2, Wout, bout, out);
}

// round 9
// speedup vs baseline: 1.0307x; 1.0307x over previous
#include <cuda_runtime.h>
#include <cuda_fp16.h>
#include <math.h>

#define NNODES 50000
#define NEDGES 800000

// ---------------- device scratch (no allocations allowed) ----------------
__device__ int     g_deg[NNODES];
__device__ int     g_rowptr[NNODES + 1];
__device__ int     g_wr[NNODES];
__device__ int     g_srcs[NEDGES];
__device__ __half2 g_hfh[NNODES * 64];  // transformed features, fp16 [N][128]
__device__ float   g_h1[NNODES * 128];  // layer-1 output (relu) = layer-2 input (fp32)
__device__ float   g_el[NNODES * 4];
__device__ float   g_er[NNODES * 4];
__device__ __half  g_wt1[128 * 128];    // W1 transposed [n][k] fp16
__device__ __half  g_wt2[128 * 128];    // W2 transposed [n][k] fp16

// ---------------- CSR build ----------------
__global__ void k_zero_deg() {
    int i = blockIdx.x * blockDim.x + threadIdx.x;
    if (i < NNODES) g_deg[i] = 0;
}

__global__ void k_hist(const int* __restrict__ dst) {
    int i = blockIdx.x * blockDim.x + threadIdx.x;
    if (i < NEDGES) atomicAdd(&g_deg[dst[i]], 1);
}

// single-block exclusive scan of g_deg -> g_rowptr (and g_wr copy)
__global__ void k_scan() {
    __shared__ int ssum[1024];
    int tid = threadIdx.x;
    const int CH = (NNODES + 1023) / 1024;   // 49
    int base = tid * CH;
    int local = 0;
    for (int i = 0; i < CH; i++) {
        int idx = base + i;
        if (idx < NNODES) local += g_deg[idx];
    }
    ssum[tid] = local;
    __syncthreads();
    for (int off = 1; off < 1024; off <<= 1) {
        int v = (tid >= off) ? ssum[tid - off] : 0;
        __syncthreads();
        ssum[tid] += v;
        __syncthreads();
    }
    int run = ssum[tid] - local;   // exclusive prefix
    for (int i = 0; i < CH; i++) {
        int idx = base + i;
        if (idx < NNODES) {
            g_rowptr[idx] = run;
            g_wr[idx] = run;
            run += g_deg[idx];
        }
    }
    if (tid == 1023) g_rowptr[NNODES] = ssum[1023];
}

__global__ void k_fill(const int* __restrict__ src, const int* __restrict__ dst) {
    int i = blockIdx.x * blockDim.x + threadIdx.x;
    if (i < NEDGES) {
        int d = dst[i];
        int p = atomicAdd(&g_wr[d], 1);
        g_srcs[p] = src[i];
    }
}

// ---------------- one-shot: W [k][n] fp32 -> g_wt [n][k] fp16 ----------------
__global__ void k_convW(const float* __restrict__ W, __half* __restrict__ wt) {
    int i = blockIdx.x * blockDim.x + threadIdx.x;   // 16384
    if (i < 128 * 128) {
        int k = i >> 7, n = i & 127;
        wt[n * 128 + k] = __float2half_rn(W[k * 128 + n]);
    }
}

// ---------------- tensor-core GEMM: hf = feat @ W (+ el/er epilogue) --------
// mma.sync.m16n8k16 fp16 inputs, fp32 accumulate. Block: 256 thr (8 warps),
// 64 rows x 128 cols per block. Warp (wm 0..3, wn 0..1) owns a 16x64 C tile.
// A: row-major k-contiguous, stride 136. B: n-major k-contiguous (sBt[n][k],
// stride 136 halves = 272 B, 16B-aligned rows) filled by PURE COPY from the
// pre-transposed fp16 g_wt. Fragment LDS.32 banks: A = 4g+(lane&3)+8ks,
// B = 4g+(lane&3) (mod 32) -> conflict-free.
#define SA_STRIDE 136
#define SB_STRIDE 136
#define GEMM_SMEM (64 * SA_STRIDE * 2 + 128 * SB_STRIDE * 2)   // 52224 bytes

__device__ __forceinline__ void mma16816(float* c, unsigned a0, unsigned a1,
                                         unsigned a2, unsigned a3,
                                         unsigned b0, unsigned b1) {
    asm volatile(
        "mma.sync.aligned.m16n8k16.row.col.f32.f16.f16.f32 "
        "{%0,%1,%2,%3}, {%4,%5,%6,%7}, {%8,%9}, {%0,%1,%2,%3};"
        : "+f"(c[0]), "+f"(c[1]), "+f"(c[2]), "+f"(c[3])
        : "r"(a0), "r"(a1), "r"(a2), "r"(a3), "r"(b0), "r"(b1));
}

__global__ void __launch_bounds__(256) k_gemm(const float* __restrict__ feat,
                                              const __half* __restrict__ wt,
                                              const float* __restrict__ al,
                                              const float* __restrict__ ar) {
    extern __shared__ __half sh[];
    __half* sA  = sh;                      // 64 x 136 (row-major, k contiguous)
    __half* sBt = sh + 64 * SA_STRIDE;     // 128 x 136 (n-major, k contiguous)
    int tid = threadIdx.x;
    int row0 = blockIdx.x * 64;

    // fill sBt: pure coalesced copy of pre-transposed fp16 W (128 rows x 16 uint4)
    const uint4* Wt4 = (const uint4*)wt;
    #pragma unroll 8
    for (int i = tid; i < 2048; i += 256) {
        int n = i >> 4, c = i & 15;
        *(uint4*)&sBt[n * SB_STRIDE + c * 8] = Wt4[i];
    }
    // fill sA = feat tile [64 x 128] fp16
    const float4* F4 = (const float4*)feat;
    #pragma unroll 2
    for (int i = tid; i < 2048; i += 256) {
        int r = i >> 5, c4 = i & 31;
        int gr = row0 + r;
        float4 f = (gr < NNODES) ? F4[gr * 32 + c4] : make_float4(0.f, 0.f, 0.f, 0.f);
        *(__half2*)&sA[r * SA_STRIDE + c4 * 4]     = __floats2half2_rn(f.x, f.y);
        *(__half2*)&sA[r * SA_STRIDE + c4 * 4 + 2] = __floats2half2_rn(f.z, f.w);
    }
    __syncthreads();

    int warp = tid >> 5, lane = tid & 31;
    int wm = warp >> 1, wn = warp & 1;
    int g = lane >> 2, t2 = (lane & 3) * 2;
    int mbase = wm * 16;
    int nbase = wn * 64;

    float acc[8][4];
    #pragma unroll
    for (int j = 0; j < 8; j++) {
        acc[j][0] = acc[j][1] = acc[j][2] = acc[j][3] = 0.f;
    }

    #pragma unroll
    for (int ks = 0; ks < 8; ks++) {
        int k0 = ks * 16;
        unsigned a0 = *(unsigned*)&sA[(mbase + g) * SA_STRIDE + k0 + t2];
        unsigned a1 = *(unsigned*)&sA[(mbase + g + 8) * SA_STRIDE + k0 + t2];
        unsigned a2 = *(unsigned*)&sA[(mbase + g) * SA_STRIDE + k0 + t2 + 8];
        unsigned a3 = *(unsigned*)&sA[(mbase + g + 8) * SA_STRIDE + k0 + t2 + 8];
        #pragma unroll
        for (int j = 0; j < 8; j++) {
            int n = nbase + j * 8 + g;
            unsigned b0 = *(unsigned*)&sBt[n * SB_STRIDE + k0 + t2];
            unsigned b1 = *(unsigned*)&sBt[n * SB_STRIDE + k0 + t2 + 8];
            mma16816(acc[j], a0, a1, a2, a3, b0, b1);
        }
    }

    // epilogue: rows r0 = row0+mbase+g, r1 = r0+8. Store fp16 hf; el/er from fp32.
    int r0 = row0 + mbase + g;
    int r1 = r0 + 8;
    __half* hf = (__half*)g_hfh;
    float el0a = 0.f, er0a = 0.f, el1a = 0.f, er1a = 0.f;  // head h0
    float el0b = 0.f, er0b = 0.f, el1b = 0.f, er1b = 0.f;  // head h0+1
    #pragma unroll
    for (int j = 0; j < 8; j++) {
        int n = nbase + j * 8 + t2;
        if (r0 < NNODES)
            *(__half2*)&hf[r0 * 128 + n] = __floats2half2_rn(acc[j][0], acc[j][1]);
        if (r1 < NNODES)
            *(__half2*)&hf[r1 * 128 + n] = __floats2half2_rn(acc[j][2], acc[j][3]);
        float av0 = __ldg(&al[n]), av1 = __ldg(&al[n + 1]);
        float rv0 = __ldg(&ar[n]), rv1 = __ldg(&ar[n + 1]);
        float pe0 = acc[j][0] * av0 + acc[j][1] * av1;
        float pr0 = acc[j][0] * rv0 + acc[j][1] * rv1;
        float pe1 = acc[j][2] * av0 + acc[j][3] * av1;
        float pr1 = acc[j][2] * rv0 + acc[j][3] * rv1;
        if (j < 4) { el0a += pe0; er0a += pr0; el1a += pe1; er1a += pr1; }
        else       { el0b += pe0; er0b += pr0; el1b += pe1; er1b += pr1; }
    }
    #pragma unroll
    for (int off = 1; off <= 2; off <<= 1) {
        el0a += __shfl_xor_sync(0xffffffffu, el0a, off);
        er0a += __shfl_xor_sync(0xffffffffu, er0a, off);
        el1a += __shfl_xor_sync(0xffffffffu, el1a, off);
        er1a += __shfl_xor_sync(0xffffffffu, er1a, off);
        el0b += __shfl_xor_sync(0xffffffffu, el0b, off);
        er0b += __shfl_xor_sync(0xffffffffu, er0b, off);
        el1b += __shfl_xor_sync(0xffffffffu, el1b, off);
        er1b += __shfl_xor_sync(0xffffffffu, er1b, off);
    }
    if ((lane & 3) == 0) {
        int h0 = wn * 2;
        if (r0 < NNODES) {
            g_el[r0 * 4 + h0]     = el0a;  g_er[r0 * 4 + h0]     = er0a;
            g_el[r0 * 4 + h0 + 1] = el0b;  g_er[r0 * 4 + h0 + 1] = er0b;
        }
        if (r1 < NNODES) {
            g_el[r1 * 4 + h0]     = el1a;  g_er[r1 * 4 + h0]     = er1a;
            g_el[r1 * 4 + h0 + 1] = el1b;  g_er[r1 * 4 + h0 + 1] = er1b;
        }
    }
}

// ---------------- warp-per-dst aggregation (R5 version — best) ----------------
__device__ __forceinline__ float lrelu(float x) { return x > 0.f ? x : 0.2f * x; }

template <bool FINAL>
__global__ void __launch_bounds__(256) k_agg(const float* __restrict__ bias,
                                             const float* __restrict__ Wout,
                                             const float* __restrict__ bout,
                                             float* __restrict__ outp) {
    int gw = (blockIdx.x * blockDim.x + threadIdx.x) >> 5;
    int lane = threadIdx.x & 31;
    if (gw >= NNODES) return;
    int n = gw;
    int start = g_rowptr[n], end = g_rowptr[n + 1];
    int h = lane >> 3;
    float er_h = __ldg(&g_er[n * 4 + h]);

    float den = 0.f;
    float4 acc = make_float4(0.f, 0.f, 0.f, 0.f);
    #pragma unroll 4
    for (int j = start; j < end; j++) {
        int s = __ldg(&g_srcs[j]);
        float el = __ldg(&g_el[s * 4 + h]);
        float x = __expf(lrelu(el + er_h));
        den += x;
        uint2 pk = __ldg((const uint2*)(g_hfh + s * 64) + lane);
        float2 v0 = __half22float2(*(__half2*)&pk.x);
        float2 v1 = __half22float2(*(__half2*)&pk.y);
        acc.x += v0.x * x; acc.y += v0.y * x;
        acc.z += v1.x * x; acc.w += v1.y * x;
    }

    float inv = 1.0f / fmaxf(den, 1e-30f);
    float4 b4 = ((const float4*)bias)[lane];
    float4 val;
    val.x = acc.x * inv + b4.x;
    val.y = acc.y * inv + b4.y;
    val.z = acc.z * inv + b4.z;
    val.w = acc.w * inv + b4.w;

    if (!FINAL) {
        val.x = fmaxf(val.x, 0.f); val.y = fmaxf(val.y, 0.f);
        val.z = fmaxf(val.z, 0.f); val.w = fmaxf(val.w, 0.f);
        ((float4*)g_h1)[n * 32 + lane] = val;
    } else {
        // mean over heads (lanes differing in bits 3,4 hold other heads, same d)
        #pragma unroll
        for (int off = 8; off <= 16; off <<= 1) {
            val.x += __shfl_xor_sync(0xffffffffu, val.x, off);
            val.y += __shfl_xor_sync(0xffffffffu, val.y, off);
            val.z += __shfl_xor_sync(0xffffffffu, val.z, off);
            val.w += __shfl_xor_sync(0xffffffffu, val.w, off);
        }
        val.x = fmaxf(val.x * 0.25f, 0.f);
        val.y = fmaxf(val.y * 0.25f, 0.f);
        val.z = fmaxf(val.z * 0.25f, 0.f);
        val.w = fmaxf(val.w * 0.25f, 0.f);
        int d0 = (lane & 7) * 4;
        float l0 = val.x * Wout[(d0 + 0) * 2 + 0] + val.y * Wout[(d0 + 1) * 2 + 0]
                 + val.z * Wout[(d0 + 2) * 2 + 0] + val.w * Wout[(d0 + 3) * 2 + 0];
        float l1 = val.x * Wout[(d0 + 0) * 2 + 1] + val.y * Wout[(d0 + 1) * 2 + 1]
                 + val.z * Wout[(d0 + 2) * 2 + 1] + val.w * Wout[(d0 + 3) * 2 + 1];
        #pragma unroll
        for (int off = 4; off >= 1; off >>= 1) {
            l0 += __shfl_xor_sync(0xffffffffu, l0, off, 8);
            l1 += __shfl_xor_sync(0xffffffffu, l1, off, 8);
        }
        if (lane == 0) {
            l0 += bout[0];
            l1 += bout[1];
            float m = fmaxf(l0, l1);
            float e0 = __expf(l0 - m), e1 = __expf(l1 - m);
            float s = e0 + e1;
            outp[n * 2 + 0] = e0 / s;
            outp[n * 2 + 1] = e1 / s;
        }
    }
}

// ---------------- launch ----------------
extern "C" void kernel_launch(void* const* d_in, const int* in_sizes, int n_in,
                              void* d_out, int out_size) {
    const float* in_feat = (const float*)d_in[0];
    const float* W1   = (const float*)d_in[1];
    const float* al1  = (const float*)d_in[2];
    const float* ar1  = (const float*)d_in[3];
    const float* b1   = (const float*)d_in[4];
    const float* W2   = (const float*)d_in[5];
    const float* al2  = (const float*)d_in[6];
    const float* ar2  = (const float*)d_in[7];
    const float* b2   = (const float*)d_in[8];
    const float* Wout = (const float*)d_in[9];
    const float* bout = (const float*)d_in[10];
    const int*   src  = (const int*)d_in[11];
    const int*   dst  = (const int*)d_in[12];
    float* out = (float*)d_out;

    cudaFuncSetAttribute(k_gemm, cudaFuncAttributeMaxDynamicSharedMemorySize, GEMM_SMEM);

    float* h1_ptr = nullptr;
    cudaGetSymbolAddress((void**)&h1_ptr, g_h1);
    __half* wt1_ptr = nullptr;
    cudaGetSymbolAddress((void**)&wt1_ptr, g_wt1);
    __half* wt2_ptr = nullptr;
    cudaGetSymbolAddress((void**)&wt2_ptr, g_wt2);

    int gemm_blocks = (NNODES + 63) / 64;
    int agg_blocks = (NNODES * 32 + 255) / 256;

    // weight pre-transpose/convert (hides among CSR kernels)
    k_convW<<<64, 256>>>(W1, wt1_ptr);
    k_convW<<<64, 256>>>(W2, wt2_ptr);

    // CSR + layer 1 (gemm1 before k_fill: no CSR dependency; keeps k_gemm in
    // the ncu capture slot for direct verification of this round's change)
    k_zero_deg<<<(NNODES + 255) / 256, 256>>>();
    k_hist<<<(NEDGES + 255) / 256, 256>>>(dst);
    k_scan<<<1, 1024>>>();
    k_gemm<<<gemm_blocks, 256, GEMM_SMEM>>>(in_feat, wt1_ptr, al1, ar1);
    k_fill<<<(NEDGES + 255) / 256, 256>>>(src, dst);
    k_agg<false><<<agg_blocks, 256>>>(b1, Wout, bout, out);

    // layer 2 + head-mean + projection + softmax
    k_gemm<<<gemm_blocks, 256, GEMM_SMEM>>>(h1_ptr, wt2_ptr, al2, ar2);
    k_agg<true><<<agg_blocks, 256>>>(b2, Wout, bout, out);
}